// round 9
// baseline (speedup 1.0000x reference)
#include <cuda_runtime.h>
#include <cuda_fp16.h>
#include <cstdint>

// Problem constants (fixed by reference)
#define BWIN   2048
#define NTOK   49
#define CDIM   384
#define HHEADS 12
#define DH     32
#define NWMASK 64
#define THREEC 1152
#define MROWS  (BWIN * NTOK)   // 100352

// Scratch (allocation-free rule: __device__ globals)
__device__ __half g_qkvh[(size_t)MROWS * THREEC];   // qkv, fp16
__device__ __half g_xh  [(size_t)MROWS * CDIM];     // x, fp16
__device__ __half g_atth[(size_t)MROWS * CDIM];     // attention out, fp16
__device__ __half g_wqh [(size_t)THREEC * CDIM];    // qkv_w, fp16
__device__ __half g_wph [(size_t)CDIM * CDIM];      // proj_w, fp16

// ---------------------------------------------------------------------------
// helpers
// ---------------------------------------------------------------------------
__device__ __forceinline__ void mma_f16_k16(float c[4],
                                            uint32_t a0, uint32_t a1, uint32_t a2, uint32_t a3,
                                            uint32_t b0, uint32_t b1) {
    asm volatile(
        "mma.sync.aligned.m16n8k16.row.col.f32.f16.f16.f32 "
        "{%0,%1,%2,%3}, {%4,%5,%6,%7}, {%8,%9}, {%0,%1,%2,%3};"
        : "+f"(c[0]), "+f"(c[1]), "+f"(c[2]), "+f"(c[3])
        : "r"(a0), "r"(a1), "r"(a2), "r"(a3), "r"(b0), "r"(b1));
}

__device__ __forceinline__ void mma_f16_k8(float c[4],
                                           uint32_t a0, uint32_t a1, uint32_t b0) {
    asm volatile(
        "mma.sync.aligned.m16n8k8.row.col.f32.f16.f16.f32 "
        "{%0,%1,%2,%3}, {%4,%5}, {%6}, {%0,%1,%2,%3};"
        : "+f"(c[0]), "+f"(c[1]), "+f"(c[2]), "+f"(c[3])
        : "r"(a0), "r"(a1), "r"(b0));
}

__device__ __forceinline__ void ldsm4(uint32_t& r0, uint32_t& r1,
                                      uint32_t& r2, uint32_t& r3, uint32_t addr) {
    asm volatile("ldmatrix.sync.aligned.m8n8.x4.shared.b16 {%0,%1,%2,%3}, [%4];"
                 : "=r"(r0), "=r"(r1), "=r"(r2), "=r"(r3) : "r"(addr));
}

__device__ __forceinline__ uint32_t smem_u32(const void* p) {
    return (uint32_t)__cvta_generic_to_shared(p);
}

// ---------------------------------------------------------------------------
// prepass: fp32 -> fp16 (rn); 8 floats per thread
// ---------------------------------------------------------------------------
__global__ void to_half_kernel(const float* __restrict__ in,
                               __half* __restrict__ out, int n8)
{
    const int i = blockIdx.x * blockDim.x + threadIdx.x;
    if (i < n8) {
        const float4 v0 = ((const float4*)in)[2 * i];
        const float4 v1 = ((const float4*)in)[2 * i + 1];
        __half2 h[4];
        h[0] = __floats2half2_rn(v0.x, v0.y);
        h[1] = __floats2half2_rn(v0.z, v0.w);
        h[2] = __floats2half2_rn(v1.x, v1.y);
        h[3] = __floats2half2_rn(v1.z, v1.w);
        ((uint4*)out)[i] = *(uint4*)h;
    }
}

// ---------------------------------------------------------------------------
// fp16 tensor-core GEMM v5b:  C = A @ W^T + bias, fp32 accum, 2 CTAs/SM
// CTA tile 128x128, BK=32 halfs, 256 threads = 8 warps (2m x 4n),
// warp tile 64x32 (acc = 64 regs/thread). Fragment-permuted smem (DENSE for
// 128 rows: kks stride is 8 mi-groups, not 16):
//   A word idx: ((kks*8  + mi)*4 + r)*32 + g2*4 + t     (2048 words/buffer)
//   B word idx: ((kks*16 + ni)*2 + r)*32 + gb*4 + t     (2048 words/buffer)
// ---------------------------------------------------------------------------
template <typename TO>
__global__ __launch_bounds__(256, 2) void gemm_f16_v5(
    const __half* __restrict__ A,
    const __half* __restrict__ W,
    const float* __restrict__ bias,
    TO* __restrict__ C,
    int Nout, int K)
{
    __shared__ __align__(16) uint32_t As[2][2048];  // 8KB x2
    __shared__ __align__(16) uint32_t Bs[2][2048];  // 8KB x2

    const int tid  = threadIdx.x;
    const int bm   = blockIdx.y * 128;
    const int bn   = blockIdx.x * 128;
    const int lane = tid & 31;
    const int warp = tid >> 5;
    const int warp_m = warp >> 2;    // 0..1 (64-row slab)
    const int warp_n = warp & 3;     // 0..3 (32-col slab)
    const int g = lane >> 2;
    const int t = lane & 3;

    // producer: row ldr = tid>>1, chunks c0 and c0+2 (8 halfs each)
    const int ldr = tid >> 1;
    const int c0  = tid & 1;

    const __half* Ab = A + (size_t)(bm + ldr) * K;
    const __half* Wb = W + (size_t)(bn + ldr) * K;

    int aoff[2], boff[2];
    {
        const int mi = ldr >> 4;
        const int lr = ldr & 15;
        const int g2 = lr & 7;
        const int hi = lr >> 3;
        const int ni = ldr >> 3;
        const int gb = ldr & 7;
#pragma unroll
        for (int i = 0; i < 2; ++i) {
            const int ch  = c0 + i * 2;        // chunk 0..3
            const int kks = ch >> 1;
            const int ph  = ch & 1;
            aoff[i] = ((kks * 8 + mi) * 4 + (hi + 2 * ph)) * 32 + g2 * 4;   // FIXED: kks*8
            boff[i] = ((kks * 16 + ni) * 2 + ph) * 32 + gb * 4;
        }
    }

    uint4 ar[2], wr[2];

    auto load_g = [&](int k0) {
        ar[0] = *(const uint4*)(Ab + k0 + c0 * 8);
        ar[1] = *(const uint4*)(Ab + k0 + c0 * 8 + 16);
        wr[0] = *(const uint4*)(Wb + k0 + c0 * 8);
        wr[1] = *(const uint4*)(Wb + k0 + c0 * 8 + 16);
    };
    auto stash = [&](int bf) {
#pragma unroll
        for (int i = 0; i < 2; ++i) {
            *(uint4*)&As[bf][aoff[i]] = ar[i];
            *(uint4*)&Bs[bf][boff[i]] = wr[i];
        }
    };

    load_g(0);
    stash(0);
    __syncthreads();

    float acc[4][4][4] = {};

    const int NS = K / 32;   // 12
    int buf = 0;
    for (int s = 0; s < NS; ++s) {
        if (s + 1 < NS) load_g((s + 1) * 32);

#pragma unroll
        for (int kk = 0; kk < 2; ++kk) {
            uint32_t af[4][4], bfr[4][2];
            const uint32_t* Ap = &As[buf][((kk * 8 + warp_m * 4) * 4) * 32 + lane];   // FIXED: kk*8
            const uint32_t* Bp = &Bs[buf][((kk * 16 + warp_n * 4) * 2) * 32 + lane];
#pragma unroll
            for (int mi = 0; mi < 4; ++mi)
#pragma unroll
                for (int r = 0; r < 4; ++r)
                    af[mi][r] = Ap[(mi * 4 + r) * 32];
#pragma unroll
            for (int ni = 0; ni < 4; ++ni) {
                bfr[ni][0] = Bp[ni * 64];
                bfr[ni][1] = Bp[ni * 64 + 32];
            }
#pragma unroll
            for (int mi = 0; mi < 4; ++mi)
#pragma unroll
                for (int ni = 0; ni < 4; ++ni)
                    mma_f16_k16(acc[mi][ni],
                                af[mi][0], af[mi][1], af[mi][2], af[mi][3],
                                bfr[ni][0], bfr[ni][1]);
        }

        if (s + 1 < NS) {
            stash(buf ^ 1);
            __syncthreads();
            buf ^= 1;
        }
    }

    // epilogue
#pragma unroll
    for (int mi = 0; mi < 4; ++mi) {
#pragma unroll
        for (int ni = 0; ni < 4; ++ni) {
            const int row = bm + warp_m * 64 + mi * 16 + g;
            const int col = bn + warp_n * 32 + ni * 8 + 2 * t;
            const float b0v = __ldg(bias + col);
            const float b1v = __ldg(bias + col + 1);
            const float v00 = acc[mi][ni][0] + b0v, v01 = acc[mi][ni][1] + b1v;
            const float v10 = acc[mi][ni][2] + b0v, v11 = acc[mi][ni][3] + b1v;
            if constexpr (sizeof(TO) == 2) {
                *(__half2*)((__half*)C + (size_t)row * Nout + col) =
                    __floats2half2_rn(v00, v01);
                *(__half2*)((__half*)C + (size_t)(row + 8) * Nout + col) =
                    __floats2half2_rn(v10, v11);
            } else {
                *(float2*)((float*)C + (size_t)row * Nout + col) = make_float2(v00, v01);
                *(float2*)((float*)C + (size_t)(row + 8) * Nout + col) = make_float2(v10, v11);
            }
        }
    }
}

// ---------------------------------------------------------------------------
// Tensor-core attention: one CTA (128 threads, 4 warps) per (window b, head h).
// (unchanged from R7 — measured ~130 us, rel_err-verified)
// ---------------------------------------------------------------------------
__global__ __launch_bounds__(128) void attn_mma(const float* __restrict__ mask)
{
    const int b = blockIdx.x;
    const int h = blockIdx.y;
    const int tid  = threadIdx.x;
    const int lane = tid & 31;
    const int w    = tid >> 5;
    const int g = lane >> 2;
    const int t = lane & 3;

    __shared__ __align__(16) __half qh[64][40];
    __shared__ __align__(16) __half kh[64][40];
    __shared__ __align__(16) __half vt[32][72];

    for (int i = tid; i < 64 * 20; i += 128) {
        ((uint32_t*)qh)[i] = 0;
        ((uint32_t*)kh)[i] = 0;
    }
    for (int i = tid; i < 32 * 36; i += 128) ((uint32_t*)vt)[i] = 0;
    __syncthreads();

    const __half* base = g_qkvh + (size_t)(b * NTOK) * THREEC + h * DH;
    for (int idx = tid; idx < NTOK * 16; idx += 128) {
        const int n  = idx >> 4;
        const int d2 = idx & 15;
        const uint32_t* p = (const uint32_t*)(base + (size_t)n * THREEC) + d2;
        const uint32_t q = p[0];
        const uint32_t k = p[CDIM / 2];
        const uint32_t v = p[CDIM];
        *(uint32_t*)&qh[n][d2 * 2] = q;
        *(uint32_t*)&kh[n][d2 * 2] = k;
        const __half2 vh = *(const __half2*)&v;
        vt[d2 * 2][n]     = __low2half(vh);
        vt[d2 * 2 + 1][n] = __high2half(vh);
    }
    __syncthreads();

    const int m0 = w * 16;
    const int r   = lane & 7;
    const int mat = lane >> 3;
    const int lrow = r + (mat & 1) * 8;
    const int lcol = (mat >> 1) * 8;

    uint32_t a[2][4];
#pragma unroll
    for (int s = 0; s < 2; ++s)
        ldsm4(a[s][0], a[s][1], a[s][2], a[s][3],
              smem_u32(&qh[m0 + lrow][lcol + s * 16]));

    float c[7][4] = {};
#pragma unroll
    for (int s = 0; s < 2; ++s) {
#pragma unroll
        for (int p = 0; p < 4; ++p) {
            uint32_t b0, b1, b2, b3;
            ldsm4(b0, b1, b2, b3, smem_u32(&kh[16 * p + lrow][lcol + s * 16]));
            mma_f16_k16(c[2 * p], a[s][0], a[s][1], a[s][2], a[s][3], b0, b2);
            if (2 * p + 1 < 7)
                mma_f16_k16(c[2 * p + 1], a[s][0], a[s][1], a[s][2], a[s][3], b1, b3);
        }
    }

    const float scale = 0.17677669529663687f;
    const float* mrow = mask + (size_t)(b & (NWMASK - 1)) * NTOK * NTOK;
    const int i1 = m0 + g;
    const int i2 = m0 + 8 + g;
    const int mi1 = (i1 < NTOK) ? i1 : NTOK - 1;
    const int mi2 = (i2 < NTOK) ? i2 : NTOK - 1;
#pragma unroll
    for (int nt = 0; nt < 7; ++nt) {
        const int j0 = nt * 8 + 2 * t;
        c[nt][0] = (j0     < NTOK) ? c[nt][0] * scale + __ldg(mrow + mi1 * NTOK + j0)     : -1e30f;
        c[nt][1] = (j0 + 1 < NTOK) ? c[nt][1] * scale + __ldg(mrow + mi1 * NTOK + j0 + 1) : -1e30f;
        c[nt][2] = (j0     < NTOK) ? c[nt][2] * scale + __ldg(mrow + mi2 * NTOK + j0)     : -1e30f;
        c[nt][3] = (j0 + 1 < NTOK) ? c[nt][3] * scale + __ldg(mrow + mi2 * NTOK + j0 + 1) : -1e30f;
    }

    float mx1 = -1e30f, mx2 = -1e30f;
#pragma unroll
    for (int nt = 0; nt < 7; ++nt) {
        mx1 = fmaxf(mx1, fmaxf(c[nt][0], c[nt][1]));
        mx2 = fmaxf(mx2, fmaxf(c[nt][2], c[nt][3]));
    }
    mx1 = fmaxf(mx1, __shfl_xor_sync(0xffffffffu, mx1, 1));
    mx1 = fmaxf(mx1, __shfl_xor_sync(0xffffffffu, mx1, 2));
    mx2 = fmaxf(mx2, __shfl_xor_sync(0xffffffffu, mx2, 1));
    mx2 = fmaxf(mx2, __shfl_xor_sync(0xffffffffu, mx2, 2));

    float s1 = 0.f, s2 = 0.f;
#pragma unroll
    for (int nt = 0; nt < 7; ++nt) {
        c[nt][0] = __expf(c[nt][0] - mx1);
        c[nt][1] = __expf(c[nt][1] - mx1);
        c[nt][2] = __expf(c[nt][2] - mx2);
        c[nt][3] = __expf(c[nt][3] - mx2);
        s1 += c[nt][0] + c[nt][1];
        s2 += c[nt][2] + c[nt][3];
    }
    s1 += __shfl_xor_sync(0xffffffffu, s1, 1);
    s1 += __shfl_xor_sync(0xffffffffu, s1, 2);
    s2 += __shfl_xor_sync(0xffffffffu, s2, 1);
    s2 += __shfl_xor_sync(0xffffffffu, s2, 2);
    const float inv1 = 1.0f / s1;
    const float inv2 = 1.0f / s2;

    uint32_t pa[7][2];
#pragma unroll
    for (int nt = 0; nt < 7; ++nt) {
        const __half2 p0 = __floats2half2_rn(c[nt][0] * inv1, c[nt][1] * inv1);
        const __half2 p1 = __floats2half2_rn(c[nt][2] * inv2, c[nt][3] * inv2);
        pa[nt][0] = *(const uint32_t*)&p0;
        pa[nt][1] = *(const uint32_t*)&p1;
    }

    float o[4][4] = {};
#pragma unroll
    for (int kc = 0; kc < 7; ++kc) {
#pragma unroll
        for (int dt = 0; dt < 4; ++dt) {
            const uint32_t bv = *(const uint32_t*)&vt[dt * 8 + g][kc * 8 + 2 * t];
            mma_f16_k8(o[dt], pa[kc][0], pa[kc][1], bv);
        }
    }

    __half* ob = g_atth + (size_t)(b * NTOK) * CDIM + h * DH;
#pragma unroll
    for (int dt = 0; dt < 4; ++dt) {
        const int d0 = dt * 8 + 2 * t;
        if (i1 < NTOK)
            *(__half2*)(ob + (size_t)i1 * CDIM + d0) = __floats2half2_rn(o[dt][0], o[dt][1]);
        if (i2 < NTOK)
            *(__half2*)(ob + (size_t)i2 * CDIM + d0) = __floats2half2_rn(o[dt][2], o[dt][3]);
    }
}

// ---------------------------------------------------------------------------
// launch
// ---------------------------------------------------------------------------
extern "C" void kernel_launch(void* const* d_in, const int* in_sizes, int n_in,
                              void* d_out, int out_size)
{
    const float* x      = (const float*)d_in[0];
    const float* mask   = (const float*)d_in[1];
    const float* qkv_w  = (const float*)d_in[2];
    const float* qkv_b  = (const float*)d_in[3];
    const float* proj_w = (const float*)d_in[4];
    const float* proj_b = (const float*)d_in[5];
    float* out = (float*)d_out;

    __half *qkvh_ptr, *xh_ptr, *atth_ptr, *wqh_ptr, *wph_ptr;
    cudaGetSymbolAddress((void**)&qkvh_ptr, g_qkvh);
    cudaGetSymbolAddress((void**)&xh_ptr,   g_xh);
    cudaGetSymbolAddress((void**)&atth_ptr, g_atth);
    cudaGetSymbolAddress((void**)&wqh_ptr,  g_wqh);
    cudaGetSymbolAddress((void**)&wph_ptr,  g_wph);

    // 0) fp32 -> fp16 prepass
    {
        const int nx = (MROWS * CDIM) / 8;
        to_half_kernel<<<(nx + 255) / 256, 256>>>(x, xh_ptr, nx);
        const int nq = (THREEC * CDIM) / 8;
        to_half_kernel<<<(nq + 255) / 256, 256>>>(qkv_w, wqh_ptr, nq);
        const int np = (CDIM * CDIM) / 8;
        to_half_kernel<<<(np + 255) / 256, 256>>>(proj_w, wph_ptr, np);
    }
    // 1) QKV GEMM: fp16 in / fp16 out
    {
        dim3 grid(THREEC / 128, MROWS / 128);   // (9, 784)
        gemm_f16_v5<__half><<<grid, 256>>>(xh_ptr, wqh_ptr, qkv_b, qkvh_ptr, THREEC, CDIM);
    }
    // 2) windowed attention (tensor cores, fp16 in/out)
    {
        dim3 grid(BWIN, HHEADS);
        attn_mma<<<grid, 128>>>(mask);
    }
    // 3) Proj GEMM: fp16 in / fp32 out
    {
        dim3 grid(CDIM / 128, MROWS / 128);     // (3, 784)
        gemm_f16_v5<float><<<grid, 256>>>(atth_ptr, wph_ptr, proj_b, out, CDIM, CDIM);
    }
}